// round 8
// baseline (speedup 1.0000x reference)
#include <cuda_runtime.h>
#include <math.h>

#define NG   512
#define IMGW 224
#define VPIX (IMGW*IMGW)
#define NPIX (3*VPIX)

// Scratch (no cudaMalloc allowed)
__device__ float  g_par[3*NG*8];   // per view, per gaussian: px,py,a,2b,c,w0,0,0
__device__ float  g_d[NPIX];       // depth maps (3 views)
__device__ float  g_t[NPIX];       // fill temp
__device__ double g_acc[2];        // sum, sumsq

__device__ __forceinline__ float ex2f(float x)
{
    float y;
    asm("ex2.approx.f32 %0, %1;" : "=f"(y) : "f"(x));
    return y;
}

// ---------------------------------------------------------------------------
// Per-gaussian preprocessing: iterated cov3d symmetrize/normalize/invert per
// view, projection, global min/max affine mapping -> screen coords.
// Double cofactors for accuracy, but NO double division (rcp + Newton).
// ---------------------------------------------------------------------------
__global__ __launch_bounds__(NG) void prep_kernel(const float* __restrict__ pos,
                                                  const float* __restrict__ cov,
                                                  const float* __restrict__ opa,
                                                  const float* __restrict__ imp)
{
    const int n = threadIdx.x;
    if (n == 0) { g_acc[0] = 0.0; g_acc[1] = 0.0; }

    float C00 = cov[n*9+0], C01 = cov[n*9+1], C02 = cov[n*9+2];
    float C10 = cov[n*9+3], C11 = cov[n*9+4], C12 = cov[n*9+5];
    float C20 = cov[n*9+6], C21 = cov[n*9+7], C22 = cov[n*9+8];
    float P[3] = { pos[n*3+0], pos[n*3+1], pos[n*3+2] };
    const float w0 = opa[n] * fminf(fmaxf(imp[n], 0.5f), 2.0f);

    // global min/max of each coordinate over the 512 gaussians
    __shared__ float smn[3][16], smx[3][16];
    __shared__ float bmn[3], bmx[3];
    const int lane = n & 31, wid = n >> 5;
    #pragma unroll
    for (int c = 0; c < 3; c++) {
        float mn = P[c], mx = P[c];
        #pragma unroll
        for (int o = 16; o > 0; o >>= 1) {
            mn = fminf(mn, __shfl_xor_sync(0xffffffffu, mn, o));
            mx = fmaxf(mx, __shfl_xor_sync(0xffffffffu, mx, o));
        }
        if (lane == 0) { smn[c][wid] = mn; smx[c][wid] = mx; }
    }
    __syncthreads();
    if (n == 0) {
        #pragma unroll
        for (int c = 0; c < 3; c++) {
            float mn = smn[c][0], mx = smx[c][0];
            for (int w = 1; w < 16; w++) {
                mn = fminf(mn, smn[c][w]);
                mx = fmaxf(mx, smx[c][w]);
            }
            bmn[c] = mn; bmx[c] = mx;
        }
    }
    __syncthreads();

    const int A0[3] = {0, 0, 2};
    const int A1[3] = {1, 2, 1};

    #pragma unroll
    for (int v = 0; v < 3; v++) {
        // symmetrize + EPS*I  (fp32, matching reference ops/order)
        float t;
        t = 0.5f*(C01 + C10); C01 = t; C10 = t;
        t = 0.5f*(C02 + C20); C02 = t; C20 = t;
        t = 0.5f*(C12 + C21); C12 = t; C21 = t;
        C00 += 1e-6f; C11 += 1e-6f; C22 += 1e-6f;
        float nrm = sqrtf(C00*C00 + C01*C01 + C02*C02 +
                          C10*C10 + C11*C11 + C12*C12 +
                          C20*C20 + C21*C21 + C22*C22);
        float den = nrm + 1e-6f;
        float rden = 1.0f / den;
        C00 *= rden; C01 *= rden; C02 *= rden;
        C10 *= rden; C11 *= rden; C12 *= rden;
        C20 *= rden; C21 *= rden; C22 *= rden;

        // symmetric 3x3 inverse: double cofactors, rcp+Newton instead of f64 div
        double d00 = C00, d01 = C01, d02 = C02, d11 = C11, d12 = C12, d22 = C22;
        double m00 = d11*d22 - d12*d12;
        double m01 = d02*d12 - d01*d22;
        double m02 = d01*d12 - d02*d11;
        double m11 = d00*d22 - d02*d02;
        double m12 = d01*d02 - d00*d12;
        double m22 = d00*d11 - d01*d01;
        double det = d00*m00 + d01*m01 + d02*m02;
        double r   = (double)(1.0f / (float)det);   // seed
        r = r * (2.0 - det * r);                    // Newton 1
        r = r * (2.0 - det * r);                    // Newton 2
        float Maa, Mab, Mbb;
        {
            const int a0 = A0[v], a1 = A1[v];
            double cof[3][3] = {{m00,m01,m02},{m01,m11,m12},{m02,m12,m22}};
            Maa = (float)(cof[a0][a0]*r);
            Mab = (float)(cof[a0][a1]*r);
            Mbb = (float)(cof[a1][a1]*r);
        }
        float a  = Maa + 1e-10f;
        float b2 = 2.0f * Mab;
        float c  = Mbb + 1e-10f;

        const int a0 = A0[v], a1 = A1[v];
        // affine map to [0,111] screen coords (replicating reference fp ops)
        float mnx = bmn[a0], mxx = bmx[a0];
        float mny = bmn[a1], mxy = bmx[a1];
        float rx  = (mxx - mnx) + 1e-6f;
        float m2x = mnx - 0.5f*rx;
        float x2x = mxx + 0.5f*rx;
        float r2x = (x2x - m2x) + 1e-6f;
        float ry  = (mxy - mny) + 1e-6f;
        float m2y = mny - 0.5f*ry;
        float x2y = mxy + 0.5f*ry;
        float r2y = (x2y - m2y) + 1e-6f;
        float px = fminf(fmaxf((P[a0] - m2x) / r2x * 111.0f, 0.0f), 111.0f);
        float py = fminf(fmaxf((P[a1] - m2y) / r2y * 111.0f, 0.0f), 111.0f);

        float* dst = &g_par[(v*NG + n)*8];
        dst[0] = px; dst[1] = py; dst[2] = a; dst[3] = b2;
        dst[4] = c;  dst[5] = w0; dst[6] = 0.0f; dst[7] = 0.0f;
    }
}

// ---------------------------------------------------------------------------
// Splat: 16x16 pixel tile, 128 threads, 2 pixels per thread (rows y, y+8).
// Two-sided compaction: full-cover gaussians (no per-pixel mask test) from the
// front, partial ones from the back.
// exp_full(f) == quad(s) - a*vx - c*vy  (analytic bilinear of a quadratic)
// dm = 0.5*(S - 512*wmin)/(wmax - wmin + eps) + S/(S + eps)
// ---------------------------------------------------------------------------
__global__ __launch_bounds__(128) void splat_kernel()
{
    const int v   = blockIdx.z;
    const int fx0 = blockIdx.x * 16, fy0 = blockIdx.y * 16;
    const int t   = threadIdx.x;
    const int lane = t & 31, wid = t >> 5;
    const int fx  = fx0 + (t & 15);
    const int fyA = fy0 + (t >> 4);
    const int fyB = fyA + 8;

    float sx, vx;
    if (fx == 0)        { sx = 0.0f;   vx = 0.0f; }
    else if (fx == 223) { sx = 111.0f; vx = 0.0f; }
    else                { sx = (float)fx * 0.5f - 0.25f; vx = 0.1875f; }
    float syA, vyA;
    if (fyA == 0)        { syA = 0.0f;   vyA = 0.0f; }
    else if (fyA == 223) { syA = 111.0f; vyA = 0.0f; }
    else                 { syA = (float)fyA * 0.5f - 0.25f; vyA = 0.1875f; }
    float syB, vyB;
    if (fyB == 223)      { syB = 111.0f; vyB = 0.0f; }
    else                 { syB = (float)fyB * 0.5f - 0.25f; vyB = 0.1875f; }

    const float hx  = (float)(fx  >> 1);
    const float hyA = (float)(fyA >> 1);
    const float hyB = (float)(fyB >> 1);

    // tile rect in half-res coords
    const float rx0 = (float)(fx0 >> 1), rx1 = (float)((fx0 + 15) >> 1);
    const float ry0 = (float)(fy0 >> 1), ry1 = (float)((fy0 + 15) >> 1);

    __shared__ float sp[NG * 8];
    __shared__ int   cF[4], cP[4];
    __shared__ int   s_front, s_back;
    if (t == 0) { s_front = 0; s_back = NG; }
    __syncthreads();

    const float* par = g_par + v * NG * 8;
    const unsigned ltm = (1u << lane) - 1u;

    for (int base = 0; base < NG; base += 128) {
        const int n = base + t;
        float2 p = *(const float2*)(par + n*8);
        float nx = fminf(fmaxf(p.x, rx0), rx1) - p.x;
        float ny = fminf(fmaxf(p.y, ry0), ry1) - p.y;
        bool keep = nx*nx + ny*ny < 400.0f;
        float fxd = fmaxf(p.x - rx0, rx1 - p.x);   // dist to farthest x-edge
        float fyd = fmaxf(p.y - ry0, ry1 - p.y);
        bool full  = keep && (fxd*fxd + fyd*fyd < 400.0f);
        bool partl = keep && !full;
        unsigned mF = __ballot_sync(0xffffffffu, full);
        unsigned mP = __ballot_sync(0xffffffffu, partl);
        if (lane == 0) { cF[wid] = __popc(mF); cP[wid] = __popc(mP); }
        __syncthreads();
        int offF = s_front, offP = 0, totF = 0, totP = 0;
        #pragma unroll
        for (int w = 0; w < 4; w++) {
            if (w < wid) { offF += cF[w]; offP += cP[w]; }
            totF += cF[w]; totP += cP[w];
        }
        int basePslot = s_back - totP;
        if (full | partl) {
            int slot = full ? (offF + __popc(mF & ltm))
                            : (basePslot + offP + __popc(mP & ltm));
            float4 q0 = *(const float4*)(par + n*8);
            float4 q1 = *(const float4*)(par + n*8 + 4);
            *(float4*)(sp + slot*8)     = q0;
            *(float4*)(sp + slot*8 + 4) = q1;
        }
        __syncthreads();
        if (t == 0) { s_front += totF; s_back -= totP; }
        __syncthreads();
    }
    const int nfull = s_front, pstart = s_back;

    const float negL2E = -1.4426950408889634f;
    const float UMIN   = -28.853900817779268f;   // -20*log2(e)

    float SA = 0.0f, mxA = -1e30f, mnA = 1e30f;
    float SB = 0.0f, mxB = -1e30f, mnB = 1e30f;

    // full-cover list: no mask test
    #pragma unroll 2
    for (int i = 0; i < nfull; i++) {
        float4 q0 = *(const float4*)(sp + i*8);      // px,py,a,2b
        float2 q1 = *(const float2*)(sp + i*8 + 4);  // c,w0
        float dx  = sx - q0.x;
        float t1  = fmaf(dx, dx, vx);
        float e0  = q0.z * t1;
        float bdx = q0.w * dx;
        float dyA = syA - q0.y;
        float fA  = fmaf(q1.x, fmaf(dyA, dyA, vyA), fmaf(bdx, dyA, e0));
        float uA  = fmaxf(fminf(fA * negL2E, 0.0f), UMIN);
        float wA  = q1.y * ex2f(uA);
        SA += wA; mxA = fmaxf(mxA, wA); mnA = fminf(mnA, wA);
        float dyB = syB - q0.y;
        float fB  = fmaf(q1.x, fmaf(dyB, dyB, vyB), fmaf(bdx, dyB, e0));
        float uB  = fmaxf(fminf(fB * negL2E, 0.0f), UMIN);
        float wB  = q1.y * ex2f(uB);
        SB += wB; mxB = fmaxf(mxB, wB); mnB = fminf(mnB, wB);
    }
    // partial list: per-pixel half-res disc test
    #pragma unroll 2
    for (int i = pstart; i < NG; i++) {
        float4 q0 = *(const float4*)(sp + i*8);
        float2 q1 = *(const float2*)(sp + i*8 + 4);
        float dxh  = hx - q0.x;
        float dxh2 = dxh * dxh;
        float dyhA = hyA - q0.y;
        float dyhB = hyB - q0.y;
        bool mA = fmaf(dyhA, dyhA, dxh2) < 400.0f;
        bool mB = fmaf(dyhB, dyhB, dxh2) < 400.0f;
        float dx  = sx - q0.x;
        float t1  = fmaf(dx, dx, vx);
        float e0  = q0.z * t1;
        float bdx = q0.w * dx;
        float dyA = syA - q0.y;
        float fA  = fmaf(q1.x, fmaf(dyA, dyA, vyA), fmaf(bdx, dyA, e0));
        float uA  = fmaxf(fminf(fA * negL2E, 0.0f), UMIN);
        float wA  = mA ? (q1.y * ex2f(uA)) : 0.0f;
        SA += wA; mxA = fmaxf(mxA, wA); mnA = fminf(mnA, wA);
        float dyB = syB - q0.y;
        float fB  = fmaf(q1.x, fmaf(dyB, dyB, vyB), fmaf(bdx, dyB, e0));
        float uB  = fmaxf(fminf(fB * negL2E, 0.0f), UMIN);
        float wB  = mB ? (q1.y * ex2f(uB)) : 0.0f;
        SB += wB; mxB = fmaxf(mxB, wB); mnB = fminf(mnB, wB);
    }

    // culled gaussians contribute exactly zero to min/max/sum
    if (nfull + (NG - pstart) < NG) {
        mnA = fminf(mnA, 0.0f); mxA = fmaxf(mxA, 0.0f);
        mnB = fminf(mnB, 0.0f); mxB = fmaxf(mxB, 0.0f);
    }

    float dmA = 0.5f*(SA - 512.0f*mnA)/((mxA - mnA) + 1e-6f) + SA/(SA + 1e-6f);
    float dmB = 0.5f*(SB - 512.0f*mnB)/((mxB - mnB) + 1e-6f) + SB/(SB + 1e-6f);
    g_d[v*VPIX + fyA*IMGW + fx] = dmA;
    g_d[v*VPIX + fyB*IMGW + fx] = dmB;
}

// ---------------------------------------------------------------------------
// Fused fill step: 7-tap H blur + 7-tap W blur + merge in one kernel,
// per-view 16-row slab with 3-row halo in smem. Step 1: g_d -> g_t.
// Step 2: g_t -> g_d, plus global sum/sumsq accumulation.
// ---------------------------------------------------------------------------
__global__ __launch_bounds__(256) void fill_kernel(int step)
{
    const int v  = blockIdx.y;
    const int r0 = blockIdx.x * 16;
    const float* in  = step ? g_t : g_d;
    float*       out = step ? g_d : g_t;

    // blur weights (double-derived, cast to float; matches f32 reference ~1e-8)
    const float K0 = 0.38292550f;
    const float K1 = 0.23226513f;
    const float K2 = 0.05182869f;
    const float K3 = 0.00425387f;

    __shared__ float sIn[22 * 224];
    __shared__ float sT [16 * 224];
    const int t = threadIdx.x;

    for (int idx = t; idx < 22*224; idx += 256) {
        int row = idx / 224;
        int x   = idx - row * 224;
        int y   = r0 - 3 + row;
        sIn[idx] = (y >= 0 && y < 224) ? in[v*VPIX + y*224 + x] : 0.0f;
    }
    __syncthreads();

    for (int idx = t; idx < 16*224; idx += 256) {
        float acc = K0 *  sIn[idx + 3*224]
                  + K1 * (sIn[idx + 2*224] + sIn[idx + 4*224])
                  + K2 * (sIn[idx + 1*224] + sIn[idx + 5*224])
                  + K3 * (sIn[idx]          + sIn[idx + 6*224]);
        sT[idx] = acc;
    }
    __syncthreads();

    double s1 = 0.0, s2 = 0.0;
    for (int idx = t; idx < 16*224; idx += 256) {
        int r = idx / 224;
        int x = idx - r * 224;
        float acc = K0 * sT[idx];
        if (x >= 1)   acc += K1 * sT[idx - 1];
        if (x >= 2)   acc += K2 * sT[idx - 2];
        if (x >= 3)   acc += K3 * sT[idx - 3];
        if (x <= 222) acc += K1 * sT[idx + 1];
        if (x <= 221) acc += K2 * sT[idx + 2];
        if (x <= 220) acc += K3 * sT[idx + 3];
        float dv  = sIn[idx + 3*224];
        float res = (dv > 1e-6f) ? dv : acc;
        out[v*VPIX + (r0 + r)*224 + x] = res;
        if (step) { s1 += (double)res; s2 += (double)res * (double)res; }
    }

    if (step) {
        #pragma unroll
        for (int o = 16; o > 0; o >>= 1) {
            s1 += __shfl_down_sync(0xffffffffu, s1, o);
            s2 += __shfl_down_sync(0xffffffffu, s2, o);
        }
        __shared__ double ws[8], ws2[8];
        int lane = t & 31, wid = t >> 5;
        if (lane == 0) { ws[wid] = s1; ws2[wid] = s2; }
        __syncthreads();
        if (t == 0) {
            double a = 0.0, b = 0.0;
            for (int w = 0; w < 8; w++) { a += ws[w]; b += ws2[w]; }
            atomicAdd(&g_acc[0], a);
            atomicAdd(&g_acc[1], b);
        }
    }
}

// ---------------------------------------------------------------------------
// Global mean / std(ddof=1) normalize
// ---------------------------------------------------------------------------
__global__ __launch_bounds__(256) void norm_kernel(float* __restrict__ out)
{
    int i = blockIdx.x*256 + threadIdx.x;
    if (i >= NPIX) return;
    double s1 = g_acc[0], s2 = g_acc[1];
    double mean = s1 / (double)NPIX;
    double var  = (s2 - s1*mean) / (double)(NPIX - 1);
    float stdf  = (float)sqrt(fmax(var, 0.0));
    out[i] = (g_d[i] - (float)mean) / (stdf + 1e-6f);
}

// ---------------------------------------------------------------------------
extern "C" void kernel_launch(void* const* d_in, const int* in_sizes, int n_in,
                              void* d_out, int out_size)
{
    const float* pos = (const float*)d_in[0];  // (1,512,3)
    const float* cov = (const float*)d_in[1];  // (1,512,3,3)
    const float* opa = (const float*)d_in[2];  // (1,512)
    const float* imp = (const float*)d_in[3];  // (1,1000)

    prep_kernel<<<1, NG>>>(pos, cov, opa, imp);

    splat_kernel<<<dim3(14, 14, 3), 128>>>();

    fill_kernel<<<dim3(14, 3), 256>>>(0);   // g_d -> g_t
    fill_kernel<<<dim3(14, 3), 256>>>(1);   // g_t -> g_d + stats

    norm_kernel<<<(NPIX + 255)/256, 256>>>((float*)d_out);
}

// round 9
// speedup vs baseline: 1.1854x; 1.1854x over previous
#include <cuda_runtime.h>
#include <math.h>

#define NG   512
#define IMGW 224
#define VPIX (IMGW*IMGW)
#define NPIX (3*VPIX)

// Scratch (no cudaMalloc allowed)
__device__ float  g_par[3*NG*8];     // per view, per gaussian: px,py,a,2b,c,w0,0,0
__device__ float  g_cov6[3*NG*6];    // per view, per gaussian: normalized cov entries
__device__ float  g_w0[NG];
__device__ float  g_bounds[6];       // bmn[3], bmx[3]
__device__ float  g_d[NPIX];         // depth maps (3 views)
__device__ float  g_t[NPIX];         // fill temp
__device__ double g_acc[2];          // sum, sumsq

// ---------------------------------------------------------------------------
// prep0: f32-only per-gaussian work (1 block). Iterated cov3d
// symmetrize/+eps/normalize chain per view; global position min/max; w0.
// ---------------------------------------------------------------------------
__global__ __launch_bounds__(NG) void prep0_kernel(const float* __restrict__ pos,
                                                   const float* __restrict__ cov,
                                                   const float* __restrict__ opa,
                                                   const float* __restrict__ imp)
{
    const int n = threadIdx.x;
    if (n == 0) { g_acc[0] = 0.0; g_acc[1] = 0.0; }

    float C00 = cov[n*9+0], C01 = cov[n*9+1], C02 = cov[n*9+2];
    float C10 = cov[n*9+3], C11 = cov[n*9+4], C12 = cov[n*9+5];
    float C20 = cov[n*9+6], C21 = cov[n*9+7], C22 = cov[n*9+8];
    float P[3] = { pos[n*3+0], pos[n*3+1], pos[n*3+2] };
    g_w0[n] = opa[n] * fminf(fmaxf(imp[n], 0.5f), 2.0f);

    // global min/max of each coordinate over the 512 gaussians
    __shared__ float smn[3][16], smx[3][16];
    const int lane = n & 31, wid = n >> 5;
    #pragma unroll
    for (int c = 0; c < 3; c++) {
        float mn = P[c], mx = P[c];
        #pragma unroll
        for (int o = 16; o > 0; o >>= 1) {
            mn = fminf(mn, __shfl_xor_sync(0xffffffffu, mn, o));
            mx = fmaxf(mx, __shfl_xor_sync(0xffffffffu, mx, o));
        }
        if (lane == 0) { smn[c][wid] = mn; smx[c][wid] = mx; }
    }
    __syncthreads();
    if (n == 0) {
        #pragma unroll
        for (int c = 0; c < 3; c++) {
            float mn = smn[c][0], mx = smx[c][0];
            for (int w = 1; w < 16; w++) {
                mn = fminf(mn, smn[c][w]);
                mx = fmaxf(mx, smx[c][w]);
            }
            g_bounds[c] = mn; g_bounds[3+c] = mx;
        }
    }

    #pragma unroll
    for (int v = 0; v < 3; v++) {
        // symmetrize + EPS*I + normalize (fp32, matching reference ops/order)
        float t;
        t = 0.5f*(C01 + C10); C01 = t; C10 = t;
        t = 0.5f*(C02 + C20); C02 = t; C20 = t;
        t = 0.5f*(C12 + C21); C12 = t; C21 = t;
        C00 += 1e-6f; C11 += 1e-6f; C22 += 1e-6f;
        float nrm = sqrtf(C00*C00 + C01*C01 + C02*C02 +
                          C10*C10 + C11*C11 + C12*C12 +
                          C20*C20 + C21*C21 + C22*C22);
        float den = nrm + 1e-6f;
        C00 /= den; C01 /= den; C02 /= den;
        C10 /= den; C11 /= den; C12 /= den;
        C20 /= den; C21 /= den; C22 /= den;

        float* dst = &g_cov6[(v*NG + n)*6];
        dst[0] = C00; dst[1] = C01; dst[2] = C02;
        dst[3] = C11; dst[4] = C12; dst[5] = C22;
    }
}

// ---------------------------------------------------------------------------
// prep1: f64 3x3 symmetric inverse per (view, gaussian), spread over 48 SMs.
// Full double division for idet (round-7 numerics). Writes g_par.
// ---------------------------------------------------------------------------
__global__ __launch_bounds__(32) void prep1_kernel(const float* __restrict__ pos)
{
    const int idx = blockIdx.x * 32 + threadIdx.x;   // [0, 1536)
    const int v = idx >> 9;       // idx / 512
    const int n = idx & (NG-1);   // idx % 512

    const int A0[3] = {0, 0, 2};
    const int A1[3] = {1, 2, 1};
    const int a0 = A0[v], a1 = A1[v];

    const float* src = &g_cov6[(v*NG + n)*6];
    double d00 = src[0], d01 = src[1], d02 = src[2];
    double d11 = src[3], d12 = src[4], d22 = src[5];

    double m00 = d11*d22 - d12*d12;
    double m01 = d02*d12 - d01*d22;
    double m02 = d01*d12 - d02*d11;
    double m11 = d00*d22 - d02*d02;
    double m12 = d01*d02 - d00*d12;
    double m22 = d00*d11 - d01*d01;
    double det = d00*m00 + d01*m01 + d02*m02;
    double idet = 1.0 / det;

    double cof[3][3] = {{m00,m01,m02},{m01,m11,m12},{m02,m12,m22}};
    float a  = (float)(cof[a0][a0]*idet) + 1e-10f;
    float b2 = 2.0f * (float)(cof[a0][a1]*idet);
    float c  = (float)(cof[a1][a1]*idet) + 1e-10f;

    // affine map to [0,111] screen coords (replicating reference fp ops)
    float mnx = g_bounds[a0],   mxx = g_bounds[3+a0];
    float mny = g_bounds[a1],   mxy = g_bounds[3+a1];
    float rx  = (mxx - mnx) + 1e-6f;
    float m2x = mnx - 0.5f*rx;
    float x2x = mxx + 0.5f*rx;
    float r2x = (x2x - m2x) + 1e-6f;
    float ry  = (mxy - mny) + 1e-6f;
    float m2y = mny - 0.5f*ry;
    float x2y = mxy + 0.5f*ry;
    float r2y = (x2y - m2y) + 1e-6f;
    float Pa  = pos[n*3 + a0];
    float Pb  = pos[n*3 + a1];
    float px = fminf(fmaxf((Pa - m2x) / r2x * 111.0f, 0.0f), 111.0f);
    float py = fminf(fmaxf((Pb - m2y) / r2y * 111.0f, 0.0f), 111.0f);

    float* dst = &g_par[(v*NG + n)*8];
    dst[0] = px; dst[1] = py; dst[2] = a; dst[3] = b2;
    dst[4] = c;  dst[5] = g_w0[n]; dst[6] = 0.0f; dst[7] = 0.0f;
}

// ---------------------------------------------------------------------------
// Splat: 16x16 pixel tile, 128 threads, 2 pixels per thread (rows y, y+8).
// Two-sided compaction: full-cover gaussians (disc covers whole tile -> no
// per-pixel mask test) from the front, partial ones from the back.
// exp_full(f) == quad(s) - a*vx - c*vy  (analytic bilinear of a quadratic)
// dm = 0.5*(S - 512*wmin)/(wmax - wmin + eps) + S/(S + eps)
// ---------------------------------------------------------------------------
__global__ __launch_bounds__(128) void splat_kernel()
{
    const int v   = blockIdx.z;
    const int fx0 = blockIdx.x * 16, fy0 = blockIdx.y * 16;
    const int t   = threadIdx.x;
    const int lane = t & 31, wid = t >> 5;
    const int fx  = fx0 + (t & 15);
    const int fyA = fy0 + (t >> 4);
    const int fyB = fyA + 8;

    float sx, vx;
    if (fx == 0)        { sx = 0.0f;   vx = 0.0f; }
    else if (fx == 223) { sx = 111.0f; vx = 0.0f; }
    else                { sx = (float)fx * 0.5f - 0.25f; vx = 0.1875f; }
    float syA, vyA;
    if (fyA == 0)        { syA = 0.0f;   vyA = 0.0f; }
    else                 { syA = (float)fyA * 0.5f - 0.25f; vyA = 0.1875f; }
    float syB, vyB;
    if (fyB == 223)      { syB = 111.0f; vyB = 0.0f; }
    else                 { syB = (float)fyB * 0.5f - 0.25f; vyB = 0.1875f; }

    const float hx  = (float)(fx  >> 1);
    const float hyA = (float)(fyA >> 1);
    const float hyB = (float)(fyB >> 1);

    // tile rect in half-res coords
    const float rx0 = (float)(fx0 >> 1), rx1 = (float)((fx0 + 15) >> 1);
    const float ry0 = (float)(fy0 >> 1), ry1 = (float)((fy0 + 15) >> 1);

    __shared__ float sp[NG * 8];
    __shared__ int   cF[4], cP[4];
    __shared__ int   s_front, s_back;
    if (t == 0) { s_front = 0; s_back = NG; }
    __syncthreads();

    const float* par = g_par + v * NG * 8;
    const unsigned ltm = (1u << lane) - 1u;

    for (int base = 0; base < NG; base += 128) {
        const int n = base + t;
        float2 p = *(const float2*)(par + n*8);
        float nx = fminf(fmaxf(p.x, rx0), rx1) - p.x;
        float ny = fminf(fmaxf(p.y, ry0), ry1) - p.y;
        bool keep = nx*nx + ny*ny < 400.0f;
        float fxd = fmaxf(p.x - rx0, rx1 - p.x);   // dist to farthest x-edge
        float fyd = fmaxf(p.y - ry0, ry1 - p.y);
        bool full  = keep && (fxd*fxd + fyd*fyd < 400.0f);
        bool partl = keep && !full;
        unsigned mF = __ballot_sync(0xffffffffu, full);
        unsigned mP = __ballot_sync(0xffffffffu, partl);
        if (lane == 0) { cF[wid] = __popc(mF); cP[wid] = __popc(mP); }
        __syncthreads();
        int offF = s_front, offP = 0, totF = 0, totP = 0;
        #pragma unroll
        for (int w = 0; w < 4; w++) {
            if (w < wid) { offF += cF[w]; offP += cP[w]; }
            totF += cF[w]; totP += cP[w];
        }
        int basePslot = s_back - totP;
        if (full | partl) {
            int slot = full ? (offF + __popc(mF & ltm))
                            : (basePslot + offP + __popc(mP & ltm));
            float4 q0 = *(const float4*)(par + n*8);
            float4 q1 = *(const float4*)(par + n*8 + 4);
            *(float4*)(sp + slot*8)     = q0;
            *(float4*)(sp + slot*8 + 4) = q1;
        }
        __syncthreads();
        if (t == 0) { s_front += totF; s_back -= totP; }
        __syncthreads();
    }
    const int nfull = s_front, pstart = s_back;

    float SA = 0.0f, mxA = -1e30f, mnA = 1e30f;
    float SB = 0.0f, mxB = -1e30f, mnB = 1e30f;

    // full-cover list: no mask test (round-7 per-pixel numerics)
    #pragma unroll 2
    for (int i = 0; i < nfull; i++) {
        float4 q0 = *(const float4*)(sp + i*8);      // px,py,a,2b
        float2 q1 = *(const float2*)(sp + i*8 + 4);  // c,w0
        float dx  = sx - q0.x;
        float dyA = syA - q0.y;
        float eA  = -(q0.z*(dx*dx + vx) + q0.w*(dx*dyA) + q1.x*(dyA*dyA + vyA));
        eA = fminf(fmaxf(eA, -20.0f), 0.0f);
        float wA = q1.y * __expf(eA);
        SA += wA; mxA = fmaxf(mxA, wA); mnA = fminf(mnA, wA);
        float dyB = syB - q0.y;
        float eB  = -(q0.z*(dx*dx + vx) + q0.w*(dx*dyB) + q1.x*(dyB*dyB + vyB));
        eB = fminf(fmaxf(eB, -20.0f), 0.0f);
        float wB = q1.y * __expf(eB);
        SB += wB; mxB = fmaxf(mxB, wB); mnB = fminf(mnB, wB);
    }
    // partial list: per-pixel half-res disc test
    #pragma unroll 2
    for (int i = pstart; i < NG; i++) {
        float4 q0 = *(const float4*)(sp + i*8);
        float2 q1 = *(const float2*)(sp + i*8 + 4);
        float dxh  = hx - q0.x;
        float dxh2 = dxh * dxh;
        float dyhA = hyA - q0.y;
        float dyhB = hyB - q0.y;
        bool mA = dyhA*dyhA + dxh2 < 400.0f;
        bool mB = dyhB*dyhB + dxh2 < 400.0f;
        float dx  = sx - q0.x;
        float wA = 0.0f, wB = 0.0f;
        if (mA) {
            float dyA = syA - q0.y;
            float eA  = -(q0.z*(dx*dx + vx) + q0.w*(dx*dyA) + q1.x*(dyA*dyA + vyA));
            eA = fminf(fmaxf(eA, -20.0f), 0.0f);
            wA = q1.y * __expf(eA);
        }
        if (mB) {
            float dyB = syB - q0.y;
            float eB  = -(q0.z*(dx*dx + vx) + q0.w*(dx*dyB) + q1.x*(dyB*dyB + vyB));
            eB = fminf(fmaxf(eB, -20.0f), 0.0f);
            wB = q1.y * __expf(eB);
        }
        SA += wA; mxA = fmaxf(mxA, wA); mnA = fminf(mnA, wA);
        SB += wB; mxB = fmaxf(mxB, wB); mnB = fminf(mnB, wB);
    }

    // culled gaussians contribute exactly zero to min/max/sum
    if (nfull + (NG - pstart) < NG) {
        mnA = fminf(mnA, 0.0f); mxA = fmaxf(mxA, 0.0f);
        mnB = fminf(mnB, 0.0f); mxB = fmaxf(mxB, 0.0f);
    }

    float dmA = 0.5f*(SA - 512.0f*mnA)/((mxA - mnA) + 1e-6f) + SA/(SA + 1e-6f);
    float dmB = 0.5f*(SB - 512.0f*mnB)/((mxB - mnB) + 1e-6f) + SB/(SB + 1e-6f);
    g_d[v*VPIX + fyA*IMGW + fx] = dmA;
    g_d[v*VPIX + fyB*IMGW + fx] = dmB;
}

// ---------------------------------------------------------------------------
// Fused fill step: 7-tap H blur + 7-tap W blur + merge in one kernel,
// per-view 8-row slab with 3-row halo in smem. step 0: g_d -> g_t.
// step 1: g_t -> g_d, plus global sum/sumsq accumulation.
// ---------------------------------------------------------------------------
__global__ __launch_bounds__(256) void fill_kernel(int step)
{
    const int v  = blockIdx.y;
    const int r0 = blockIdx.x * 8;
    const float* in  = step ? g_t : g_d;
    float*       out = step ? g_d : g_t;

    const float K0 = 0.38292550f;
    const float K1 = 0.23226513f;
    const float K2 = 0.05182869f;
    const float K3 = 0.00425387f;

    __shared__ float sIn[14 * 224];
    __shared__ float sT [8 * 224];
    const int t = threadIdx.x;

    for (int idx = t; idx < 14*224; idx += 256) {
        int row = idx / 224;
        int x   = idx - row * 224;
        int y   = r0 - 3 + row;
        sIn[idx] = (y >= 0 && y < 224) ? in[v*VPIX + y*224 + x] : 0.0f;
    }
    __syncthreads();

    for (int idx = t; idx < 8*224; idx += 256) {
        float acc = K0 *  sIn[idx + 3*224]
                  + K1 * (sIn[idx + 2*224] + sIn[idx + 4*224])
                  + K2 * (sIn[idx + 1*224] + sIn[idx + 5*224])
                  + K3 * (sIn[idx]          + sIn[idx + 6*224]);
        sT[idx] = acc;
    }
    __syncthreads();

    double s1 = 0.0, s2 = 0.0;
    for (int idx = t; idx < 8*224; idx += 256) {
        int r = idx / 224;
        int x = idx - r * 224;
        float acc = K0 * sT[idx];
        if (x >= 1)   acc += K1 * sT[idx - 1];
        if (x >= 2)   acc += K2 * sT[idx - 2];
        if (x >= 3)   acc += K3 * sT[idx - 3];
        if (x <= 222) acc += K1 * sT[idx + 1];
        if (x <= 221) acc += K2 * sT[idx + 2];
        if (x <= 220) acc += K3 * sT[idx + 3];
        float dv  = sIn[idx + 3*224];
        float res = (dv > 1e-6f) ? dv : acc;
        out[v*VPIX + (r0 + r)*224 + x] = res;
        if (step) { s1 += (double)res; s2 += (double)res * (double)res; }
    }

    if (step) {
        #pragma unroll
        for (int o = 16; o > 0; o >>= 1) {
            s1 += __shfl_down_sync(0xffffffffu, s1, o);
            s2 += __shfl_down_sync(0xffffffffu, s2, o);
        }
        __shared__ double ws[8], ws2[8];
        int lane = t & 31, wid = t >> 5;
        if (lane == 0) { ws[wid] = s1; ws2[wid] = s2; }
        __syncthreads();
        if (t == 0) {
            double a = 0.0, b = 0.0;
            for (int w = 0; w < 8; w++) { a += ws[w]; b += ws2[w]; }
            atomicAdd(&g_acc[0], a);
            atomicAdd(&g_acc[1], b);
        }
    }
}

// ---------------------------------------------------------------------------
// Global mean / std(ddof=1) normalize
// ---------------------------------------------------------------------------
__global__ __launch_bounds__(256) void norm_kernel(float* __restrict__ out)
{
    int i = blockIdx.x*256 + threadIdx.x;
    if (i >= NPIX) return;
    double s1 = g_acc[0], s2 = g_acc[1];
    double mean = s1 / (double)NPIX;
    double var  = (s2 - s1*mean) / (double)(NPIX - 1);
    float stdf  = (float)sqrt(fmax(var, 0.0));
    out[i] = (g_d[i] - (float)mean) / (stdf + 1e-6f);
}

// ---------------------------------------------------------------------------
extern "C" void kernel_launch(void* const* d_in, const int* in_sizes, int n_in,
                              void* d_out, int out_size)
{
    const float* pos = (const float*)d_in[0];  // (1,512,3)
    const float* cov = (const float*)d_in[1];  // (1,512,3,3)
    const float* opa = (const float*)d_in[2];  // (1,512)
    const float* imp = (const float*)d_in[3];  // (1,1000)

    prep0_kernel<<<1, NG>>>(pos, cov, opa, imp);
    prep1_kernel<<<48, 32>>>(pos);

    splat_kernel<<<dim3(14, 14, 3), 128>>>();

    fill_kernel<<<dim3(28, 3), 256>>>(0);   // g_d -> g_t
    fill_kernel<<<dim3(28, 3), 256>>>(1);   // g_t -> g_d + stats

    norm_kernel<<<(NPIX + 255)/256, 256>>>((float*)d_out);
}